// round 13
// baseline (speedup 1.0000x reference)
#include <cuda_runtime.h>
#include <math.h>
#include <stdint.h>

#define N_SPK 65536
#define HID   1024
#define DUP   2048
#define UMAT  3072
#define LN_EPS 1e-5f

#define FUSED_BLOCKS 296                 // 148 SMs x 2 resident blocks (exact fit)
#define WARPS_TOTAL  (FUSED_BLOCKS * 8)  // 2368 persistent warps
#define CTX_BLOCKS   (FUSED_BLOCKS / 8)  // 37 combining blocks x 8 partials
#define H2_BLOCKS    256                 // blocks running the slice-2 GEMV

// ---- scratch (allocation-free: __device__ globals) ----
__device__ float g_query[HID];
__device__ float g_wm[FUSED_BLOCKS];              // per-BLOCK softmax max
__device__ float g_ws[FUSED_BLOCKS];              // per-BLOCK softmax sum
__device__ float g_wv[FUSED_BLOCKS * HID];        // per-BLOCK weighted vectors (1.2 MB)
__device__ float g_context[HID];
__device__ float g_hacc[DUP];                     // split-K partials, layer 1
__device__ float g_oacc[HID];                     // split-K partials, layer 2
__device__ unsigned int g_tick1 = 0;              // grid barrier 1 (reset by k_query)
__device__ unsigned int g_tick2 = 0;              // grid barrier 2 (reset by k_query)

__device__ __forceinline__ float warp_sum(float v) {
#pragma unroll
    for (int o = 16; o > 0; o >>= 1) v += __shfl_xor_sync(0xffffffffu, v, o);
    return v;
}
__device__ __forceinline__ float warp_max(float v) {
#pragma unroll
    for (int o = 16; o > 0; o >>= 1) v = fmaxf(v, __shfl_xor_sync(0xffffffffu, v, o));
    return v;
}
__device__ __forceinline__ float dot4(float4 a, float4 b) {
    return a.x * b.x + a.y * b.y + a.z * b.z + a.w * b.w;
}
__device__ __forceinline__ uint32_t smem_u32(const void* p) {
    return (uint32_t)__cvta_generic_to_shared(p);
}
__device__ __forceinline__ void cp_async16(uint32_t dst, const void* src) {
    asm volatile("cp.async.cg.shared.global [%0], [%1], 16;\n" :: "r"(dst), "l"(src));
}
__device__ __forceinline__ void cp_commit_wait_all() {
    asm volatile("cp.async.commit_group;\n");
    asm volatile("cp.async.wait_group 0;\n" ::: "memory");
}

// K1: query = W_attn @ u_t (128 blocks x 8 rows) with cp.async staging.
// Also zeros accumulators and both grid-barrier tickets.
__global__ void k_query(const float* __restrict__ W_attn, const float* __restrict__ u_t) {
    __shared__ float tile[8 * HID];
    __shared__ float sm[64];
    int gt = blockIdx.x * 256 + threadIdx.x;
    if (gt < HID) g_context[gt] = 0.f;
    if (gt < DUP) g_hacc[gt] = 0.f;
    if (gt < HID) g_oacc[gt] = 0.f;
    if (gt == 0) { g_tick1 = 0; g_tick2 = 0; }

    int t = threadIdx.x;
    int lane = t & 31, wid = t >> 5;
    int row0 = blockIdx.x * 8;

#pragma unroll
    for (int r = 0; r < 8; r++)
        cp_async16(smem_u32(&tile[r * HID + t * 4]),
                   W_attn + (size_t)(row0 + r) * HID + t * 4);
    float4 b = ((const float4*)u_t)[t];
    cp_commit_wait_all();
    __syncthreads();

    float p[8];
#pragma unroll
    for (int r = 0; r < 8; r++) p[r] = dot4(((const float4*)tile)[r * 256 + t], b);
#pragma unroll
    for (int r = 0; r < 8; r++) {
        float v = warp_sum(p[r]);
        if (lane == 0) sm[r * 8 + wid] = v;
    }
    __syncthreads();
    if (t < 64) {
        float v = sm[t];
#pragma unroll
        for (int o = 4; o > 0; o >>= 1) v += __shfl_xor_sync(0xffffffffu, v, o, 8);
        if ((t & 7) == 0) g_query[row0 + (t >> 3)] = v;
    }
}

// K2: FUSED persistent pass: copy + logits + online-softmax context partials
//  -> grid barrier 1 -> blocks 0..36 combine g_context
//  -> grid barrier 2 -> blocks 0..255 run the W1 slice-2 GEMV into g_hacc.
__global__ void __launch_bounds__(256, 2)
k_fused(const float* __restrict__ SE, float* __restrict__ out,
        const float* __restrict__ W1) {
    __shared__ float q[HID];
    __shared__ float s_acc[HID];
    __shared__ float tile[8 * HID];       // 32 KB, used in the h2 phase
    __shared__ float s_m[8], s_s[8];
    __shared__ float red[8];
    __shared__ float fin[2];
    __shared__ float e_sh[8];
    __shared__ float sm2[64];
    for (int i = threadIdx.x; i < HID; i += blockDim.x) q[i] = g_query[i];
    __syncthreads();

    int warp = threadIdx.x >> 5, lane = threadIdx.x & 31;
    int gw = blockIdx.x * 8 + warp;

    const float4* se4  = (const float4*)SE;
    float4*       out4 = (float4*)out;
    const float4* q4   = (const float4*)q;

    float4 v0[8], v1[8], acc[8];
#pragma unroll
    for (int k = 0; k < 8; k++) acc[k] = make_float4(0.f, 0.f, 0.f, 0.f);
    float m = -INFINITY, s = 0.f;

    {
        size_t rb = (size_t)gw * (HID / 4);
#pragma unroll
        for (int k = 0; k < 8; k++) v0[k] = __ldcs(&se4[rb + k * 32 + lane]);
    }

    for (int row = gw; row < N_SPK; row += WARPS_TOTAL) {
        size_t rb = (size_t)row * (HID / 4);
        int nrow = row + WARPS_TOTAL;
        if (nrow < N_SPK) {
            size_t nb = (size_t)nrow * (HID / 4);
#pragma unroll
            for (int k = 0; k < 8; k++) v1[k] = __ldcs(&se4[nb + k * 32 + lane]);
        }
        float p = 0.f;
#pragma unroll
        for (int k = 0; k < 8; k++) p += dot4(v0[k], q4[k * 32 + lane]);
        p = warp_sum(p);

        float mn = fmaxf(m, p);
        float sc = expf(m - mn);        // first iter: exp(-inf)=0
        float wt = expf(p - mn);
        s = s * sc + wt;
        m = mn;
#pragma unroll
        for (int k = 0; k < 8; k++) {
            __stcs(&out4[rb + k * 32 + lane], v0[k]);
            acc[k].x = fmaf(acc[k].x, sc, wt * v0[k].x);
            acc[k].y = fmaf(acc[k].y, sc, wt * v0[k].y);
            acc[k].z = fmaf(acc[k].z, sc, wt * v0[k].z);
            acc[k].w = fmaf(acc[k].w, sc, wt * v0[k].w);
        }
#pragma unroll
        for (int k = 0; k < 8; k++) v0[k] = v1[k];
    }

    // ---- block-level merge of 8 warp partials ----
    if (lane == 0) { s_m[warp] = m; s_s[warp] = s; }
    __syncthreads();
    float Mb = s_m[0];
#pragma unroll
    for (int j = 1; j < 8; j++) Mb = fmaxf(Mb, s_m[j]);
    float Sb = 0.f;
#pragma unroll
    for (int j = 0; j < 8; j++) Sb += s_s[j] * expf(s_m[j] - Mb);
    float scw = expf(m - Mb);

    float4* sa4 = (float4*)s_acc;
    for (int w = 0; w < 8; w++) {
        if (warp == w) {
#pragma unroll
            for (int k = 0; k < 8; k++) {
                int c = k * 32 + lane;
                float4 r;
                if (w == 0) r = make_float4(0.f, 0.f, 0.f, 0.f);
                else        r = sa4[c];
                r.x += acc[k].x * scw;
                r.y += acc[k].y * scw;
                r.z += acc[k].z * scw;
                r.w += acc[k].w * scw;
                sa4[c] = r;
            }
        }
        __syncthreads();
    }

    int t = threadIdx.x;
    if (t == 0) { g_wm[blockIdx.x] = Mb; g_ws[blockIdx.x] = Sb; }
    ((float4*)g_wv)[(size_t)blockIdx.x * (HID / 4) + t] = sa4[t];

    // ---- grid barrier 1 (all 296 blocks co-resident) ----
    __threadfence();
    __syncthreads();
    if (t == 0) {
        atomicAdd(&g_tick1, 1u);
        while (atomicAdd(&g_tick1, 0u) < FUSED_BLOCKS) __nanosleep(64);
    }
    __syncthreads();
    __threadfence();

    // ---- combine phase (blocks 0..36), data L2-hot ----
    if (blockIdx.x < CTX_BLOCKS) {
        float m0 = (t < FUSED_BLOCKS) ? g_wm[t] : -INFINITY;
        float m1 = (t + 256 < FUSED_BLOCKS) ? g_wm[t + 256] : -INFINITY;
        float mm = fmaxf(m0, m1);
        mm = warp_max(mm);
        if (lane == 0) red[warp] = mm;
        __syncthreads();
        if (t < 32) {
            float x = (t < 8) ? red[t] : -INFINITY;
            x = warp_max(x);
            if (t == 0) fin[0] = x;
        }
        __syncthreads();
        float M = fin[0];

        float ss = 0.f;
        if (t < FUSED_BLOCKS)       ss += g_ws[t] * expf(m0 - M);
        if (t + 256 < FUSED_BLOCKS) ss += g_ws[t + 256] * expf(m1 - M);
        ss = warp_sum(ss);
        __syncthreads();
        if (lane == 0) red[warp] = ss;
        __syncthreads();
        if (t < 32) {
            float x = (t < 8) ? red[t] : 0.f;
            x = warp_sum(x);
            if (t == 0) fin[1] = x;
        }
        __syncthreads();
        float invS = 1.f / fin[1];

        int wbase = blockIdx.x * 8;
        if (t < 8) e_sh[t] = expf(g_wm[wbase + t] - M) * invS;
        __syncthreads();

        const float4* v4 = (const float4*)g_wv;
        float4 accc = make_float4(0.f, 0.f, 0.f, 0.f);
#pragma unroll
        for (int j = 0; j < 8; j++) {
            float4 v = v4[(size_t)(wbase + j) * (HID / 4) + t];
            float ee = e_sh[j];
            accc.x = fmaf(ee, v.x, accc.x);
            accc.y = fmaf(ee, v.y, accc.y);
            accc.z = fmaf(ee, v.z, accc.z);
            accc.w = fmaf(ee, v.w, accc.w);
        }
        float* ctx = g_context + t * 4;
        atomicAdd(ctx + 0, accc.x);
        atomicAdd(ctx + 1, accc.y);
        atomicAdd(ctx + 2, accc.z);
        atomicAdd(ctx + 3, accc.w);
    }

    // ---- grid barrier 2: context complete ----
    __threadfence();
    __syncthreads();
    if (t == 0) {
        atomicAdd(&g_tick2, 1u);
        while (atomicAdd(&g_tick2, 0u) < FUSED_BLOCKS) __nanosleep(64);
    }
    __syncthreads();
    __threadfence();

    if (blockIdx.x >= H2_BLOCKS) return;

    // ---- h2 phase: W1 slice-2 GEMV vs context (blocks 0..255, 8 rows each) ----
    {
        int row0 = blockIdx.x * 8;
#pragma unroll
        for (int r = 0; r < 8; r++)
            cp_async16(smem_u32(&tile[r * HID + t * 4]),
                       W1 + (size_t)(row0 + r) * UMAT + 2048 + t * 4);
        float4 b = ((const float4*)g_context)[t];
        cp_commit_wait_all();
        __syncthreads();

        float p[8];
#pragma unroll
        for (int r = 0; r < 8; r++) p[r] = dot4(((const float4*)tile)[r * 256 + t], b);
#pragma unroll
        for (int r = 0; r < 8; r++) {
            float v = warp_sum(p[r]);
            if (lane == 0) sm2[r * 8 + warp] = v;
        }
        __syncthreads();
        if (t < 64) {
            float v = sm2[t];
#pragma unroll
            for (int o = 4; o > 0; o >>= 1) v += __shfl_xor_sync(0xffffffffu, v, o, 8);
            if ((t & 7) == 0) atomicAdd(&g_hacc[row0 + (t >> 3)], v);
        }
    }
}

// K4a: layer-1 partials for K-slices 0 and 1 (u_t, SE[s_i]) — runs on the
// side stream concurrently with k_fused. 512 blocks.
__global__ void __launch_bounds__(256)
k_h01(const float* __restrict__ W1,
      const float* __restrict__ u_t, const float* __restrict__ SE,
      const int* __restrict__ s_i_p) {
    __shared__ float tile[8 * HID];       // 32 KB
    __shared__ float sm[64];
    int slice = blockIdx.x >> 8;          // 0..1
    int rg    = blockIdx.x & 255;         // 0..255
    int t = threadIdx.x;
    int lane = t & 31, wid = t >> 5;

    int row0 = rg * 8;
    int celt = slice * 1024 + t * 4;
#pragma unroll
    for (int r = 0; r < 8; r++)
        cp_async16(smem_u32(&tile[r * HID + t * 4]),
                   W1 + (size_t)(row0 + r) * UMAT + celt);

    const float* src = (slice == 0) ? u_t : (SE + (size_t)(*s_i_p) * HID);
    float4 b = ((const float4*)src)[t];

    cp_commit_wait_all();
    __syncthreads();

    float p[8];
#pragma unroll
    for (int r = 0; r < 8; r++) p[r] = dot4(((const float4*)tile)[r * 256 + t], b);
#pragma unroll
    for (int r = 0; r < 8; r++) {
        float v = warp_sum(p[r]);
        if (lane == 0) sm[r * 8 + wid] = v;
    }
    __syncthreads();
    if (t < 64) {
        float v = sm[t];
#pragma unroll
        for (int o = 4; o > 0; o >>= 1) v += __shfl_xor_sync(0xffffffffu, v, o, 8);
        if ((t & 7) == 0) atomicAdd(&g_hacc[row0 + (t >> 3)], v);
    }
}

// K5: split-K layer-2 partials. 256 blocks = 2 K-slices x 128 groups of 8 rows.
__global__ void k_o(const float* __restrict__ W2, const float* __restrict__ b1) {
    __shared__ float tile[8 * HID];       // 32 KB
    __shared__ float h[HID];
    __shared__ float sm[64];
    int slice = blockIdx.x >> 7;          // 0..1
    int rg    = blockIdx.x & 127;         // 0..127
    int t = threadIdx.x;
    int lane = t & 31, wid = t >> 5;

    int row0 = rg * 8;
    int celt = slice * 1024 + t * 4;
#pragma unroll
    for (int r = 0; r < 8; r++)
        cp_async16(smem_u32(&tile[r * HID + t * 4]),
                   W2 + (size_t)(row0 + r) * DUP + celt);

    {
        float4 aa = ((const float4*)g_hacc)[slice * 256 + t];
        float4 bb = ((const float4*)b1)[slice * 256 + t];
        float4 r;
        float x;
        x = aa.x + bb.x; r.x = 0.5f * x * (1.f + erff(x * 0.70710678118654752f));
        x = aa.y + bb.y; r.y = 0.5f * x * (1.f + erff(x * 0.70710678118654752f));
        x = aa.z + bb.z; r.z = 0.5f * x * (1.f + erff(x * 0.70710678118654752f));
        x = aa.w + bb.w; r.w = 0.5f * x * (1.f + erff(x * 0.70710678118654752f));
        ((float4*)h)[t] = r;
    }
    cp_commit_wait_all();
    __syncthreads();

    float4 b = ((const float4*)h)[t];
    float p[8];
#pragma unroll
    for (int r = 0; r < 8; r++) p[r] = dot4(((const float4*)tile)[r * 256 + t], b);
#pragma unroll
    for (int r = 0; r < 8; r++) {
        float v = warp_sum(p[r]);
        if (lane == 0) sm[r * 8 + wid] = v;
    }
    __syncthreads();
    if (t < 64) {
        float v = sm[t];
#pragma unroll
        for (int o = 4; o > 0; o >>= 1) v += __shfl_xor_sync(0xffffffffu, v, o, 8);
        if ((t & 7) == 0) atomicAdd(&g_oacc[row0 + (t >> 3)], v);
    }
}

// K6: LayerNorm over (g_oacc + b2) + residual scatter of row s_i.
__global__ void k_ln_scatter(const float* __restrict__ SE,
                             const float* __restrict__ b2,
                             const float* __restrict__ gamma,
                             const float* __restrict__ beta,
                             const int* __restrict__ s_i_p,
                             float* __restrict__ out) {
    __shared__ float sm[32];
    __shared__ float s_mu, s_rstd;
    int t = threadIdx.x;
    float o = g_oacc[t] + b2[t];

    float v = warp_sum(o);
    if ((t & 31) == 0) sm[t >> 5] = v;
    __syncthreads();
    if (t < 32) {
        v = warp_sum(sm[t]);
        if (t == 0) s_mu = v * (1.f / 1024.f);
    }
    __syncthreads();

    float d = o - s_mu;
    v = warp_sum(d * d);
    __syncthreads();
    if ((t & 31) == 0) sm[t >> 5] = v;
    __syncthreads();
    if (t < 32) {
        v = warp_sum(sm[t]);
        if (t == 0) s_rstd = rsqrtf(v * (1.f / 1024.f) + LN_EPS);
    }
    __syncthreads();

    int si = *s_i_p;
    float hs = SE[(size_t)si * HID + t];
    out[(size_t)si * HID + t] = hs + d * s_rstd * gamma[t] + beta[t];
}

extern "C" void kernel_launch(void* const* d_in, const int* in_sizes, int n_in,
                              void* d_out, int out_size) {
    const float* u_t    = (const float*)d_in[0];
    const float* SE     = (const float*)d_in[1];
    const float* W_attn = (const float*)d_in[2];
    const float* W1     = (const float*)d_in[3];
    const float* b1     = (const float*)d_in[4];
    const float* W2     = (const float*)d_in[5];
    const float* b2     = (const float*)d_in[6];
    const float* gamma  = (const float*)d_in[7];
    const float* beta   = (const float*)d_in[8];
    const int*   s_i    = (const int*)d_in[9];
    float* out = (float*)d_out;

    static cudaStream_t s_side = nullptr;
    static cudaEvent_t  ev_q = nullptr, ev_h = nullptr;
    if (s_side == nullptr) {
        cudaStreamCreateWithFlags(&s_side, cudaStreamNonBlocking);
        cudaEventCreateWithFlags(&ev_q, cudaEventDisableTiming);
        cudaEventCreateWithFlags(&ev_h, cudaEventDisableTiming);
    }

    // main stream
    k_query<<<HID / 8, 256>>>(W_attn, u_t);
    cudaEventRecord(ev_q, 0);

    // side stream: W1 slices 0/1 GEMV overlapped with the big fused pass
    cudaStreamWaitEvent(s_side, ev_q, 0);
    k_h01<<<2 * 256, 256, 0, s_side>>>(W1, u_t, SE, s_i);
    cudaEventRecord(ev_h, s_side);

    // main stream: fused bank pass (grid barriers + context combine + slice-2 GEMV)
    k_fused<<<FUSED_BLOCKS, 256>>>(SE, out, W1);

    // join side stream, then layer 2 + LN
    cudaStreamWaitEvent(0, ev_h, 0);
    k_o<<<2 * 128, 256>>>(W2, b1);
    k_ln_scatter<<<1, 1024>>>(SE, b2, gamma, beta, s_i, out);
}